// round 1
// baseline (speedup 1.0000x reference)
#include <cuda_runtime.h>
#include <cuda_bf16.h>
#include <math.h>

// Problem sizes (fixed by the reference)
#define BB 8
#define LL 2048
#define DD 512
#define MT (BB*LL)          // 16384 rows
#define SZ ((long long)MT*DD)

// ---------------- scratch (device globals; no allocation allowed) ----------------
__device__ float g_xc[MT*DD];        // conv output
__device__ float g_h1[2*MT*DD];      // gelu(xc@{eta_w1,alpha_w1})
__device__ float g_q[MT*DD];         // normalized q
__device__ float g_hm[MT*DD];        // reused: raw q-gemm out, then gelu(scan stage1)
__device__ float g_accum[MT + 2*LL]; // [0:MT) hs rowsums, [MT:MT+LL) eta sum, [MT+LL:) alpha sum
__device__ float g_ps[2*LL];         // [0:LL) p,  [LL:2LL) s
__device__ float g_qsum[MT];         // rowsum of q

__device__ __forceinline__ float gelu_exact(float x) {
    return 0.5f * x * (1.0f + erff(x * 0.70710678118654752f));
}
__device__ __forceinline__ float sigm(float x) {
    return 1.0f / (1.0f + expf(-x));
}

// ---------------- zero accumulators ----------------
__global__ void zero_kernel(float* a, int n) {
    int i = blockIdx.x * blockDim.x + threadIdx.x;
    if (i < n) a[i] = 0.0f;
}

// ---------------- causal depthwise conv (k=4, left pad 3) + bias ----------------
__global__ void conv_kernel(const float* __restrict__ x, const float* __restrict__ w,
                            const float* __restrict__ bias, float* __restrict__ xc) {
    int idx = blockIdx.x * blockDim.x + threadIdx.x;   // over MT*128 (float4 along D)
    if (idx >= MT * (DD/4)) return;
    int d4 = idx & 127;          // float4 index along D
    int r  = idx >> 7;           // row = b*L + l
    int l  = r & (LL-1);
    int d  = d4 * 4;
    float4 out = *(const float4*)(bias + d);
    #pragma unroll
    for (int k = 0; k < 4; k++) {
        int li = l + k - 3;
        if (li >= 0) {
            float4 xv = *(const float4*)(x + (long long)(r + k - 3) * DD + d);
            out.x += xv.x * w[(d+0)*4 + k];
            out.y += xv.y * w[(d+1)*4 + k];
            out.z += xv.z * w[(d+2)*4 + k];
            out.w += xv.w * w[(d+3)*4 + k];
        }
    }
    *(float4*)(xc + (long long)r * DD + d) = out;
}

// ---------------- l2norm rows + rowsum ----------------
__global__ void l2norm_kernel(const float* __restrict__ G, float* __restrict__ q,
                              float* __restrict__ qsum) {
    int r = blockIdx.x;
    int t = threadIdx.x;    // 128 threads, 1 float4 each
    float4 v = ((const float4*)(G + (long long)r * DD))[t];
    float ss = v.x*v.x + v.y*v.y + v.z*v.z + v.w*v.w;
    float sg = v.x + v.y + v.z + v.w;
    #pragma unroll
    for (int o = 16; o > 0; o >>= 1) {
        ss += __shfl_down_sync(0xffffffffu, ss, o);
        sg += __shfl_down_sync(0xffffffffu, sg, o);
    }
    __shared__ float sh_ss[4], sh_sg[4], sh_scale;
    int w = t >> 5;
    if ((t & 31) == 0) { sh_ss[w] = ss; sh_sg[w] = sg; }
    __syncthreads();
    if (t == 0) {
        float S = sh_ss[0] + sh_ss[1] + sh_ss[2] + sh_ss[3];
        float Gs = sh_sg[0] + sh_sg[1] + sh_sg[2] + sh_sg[3];
        float scale = 1.0f / fmaxf(sqrtf(S), 1e-12f);
        sh_scale = scale;
        qsum[r] = Gs * scale;
    }
    __syncthreads();
    float sc = sh_scale;
    float4 o4 = { v.x*sc, v.y*sc, v.z*sc, v.w*sc };
    ((float4*)(q + (long long)r * DD))[t] = o4;
}

// ---------------- serial scalar scan for p_t, s_t ----------------
__global__ void scan_kernel(const float* __restrict__ red, float* __restrict__ PS) {
    if (threadIdx.x == 0 && blockIdx.x == 0) {
        const float inv = 1.0f / (float)(BB * DD);
        float p = 1.0f, s = 0.0f;
        for (int t = 0; t < LL; t++) {
            PS[t]      = p;
            PS[LL + t] = s;
            float e = red[t] * inv;        // eta mean
            float a = red[LL + t] * inv;   // alpha mean
            s = s * a - 0.01f * e;
            p = p * a;
        }
    }
}

// ---------------- generic GEMM with fused epilogues ----------------
// EPI 0: C = acc
// EPI 1: C = gelu(acc)
// EPI 2: v = sigmoid(aux[r,c] + acc); atomicAdd red[l] += v (no store)
// EPI 3: h = gelu(P[l]*acc + S[l]*vin[r]); C = h; atomicAdd red0[r] += h
// EPI 4: C = aux[r,c] + P[l]*acc + S[l]*vin[r]
template<int EPI, bool TB>
__global__ __launch_bounds__(256)
void gemm_kernel(const float* __restrict__ A, long long Astride,
                 const float* __restrict__ B0, const float* __restrict__ B1,
                 float* C0, float* C1,
                 const float* __restrict__ aux,   // xc (EPI2) / q (EPI4)
                 const float* __restrict__ P, const float* __restrict__ S,
                 const float* __restrict__ vin,   // qsum (EPI3) / hs (EPI4)
                 float* red0, float* red1,
                 int M, int N, int K) {
    constexpr int BM = 128, BN = 128, BK = 16;
    __shared__ float As[BK][BM + 4];
    __shared__ float Bs[BK][BN + 4];
    const int tid = threadIdx.x;
    const int tx = tid & 15, ty = tid >> 4;
    const int rowBase = blockIdx.y * BM;
    const int colBase = blockIdx.x * BN;
    const int z = blockIdx.z;
    const float* Ab = A + (long long)z * Astride;
    const float* B  = z ? B1 : B0;
    float* C        = z ? C1 : C0;

    float acc[8][8];
    #pragma unroll
    for (int i = 0; i < 8; i++)
        #pragma unroll
        for (int j = 0; j < 8; j++) acc[i][j] = 0.0f;

    for (int k0 = 0; k0 < K; k0 += BK) {
        #pragma unroll
        for (int i = 0; i < 2; i++) {
            int li = tid + i * 256;
            int ar = li >> 2;
            int ak = (li & 3) * 4;
            float4 v = *(const float4*)(Ab + (long long)(rowBase + ar) * K + k0 + ak);
            As[ak+0][ar] = v.x; As[ak+1][ar] = v.y; As[ak+2][ar] = v.z; As[ak+3][ar] = v.w;
        }
        if (!TB) {
            #pragma unroll
            for (int i = 0; i < 2; i++) {
                int li = tid + i * 256;
                int bk = li >> 5;
                int bc = (li & 31) * 4;
                float4 v = *(const float4*)(B + (long long)(k0 + bk) * N + colBase + bc);
                *(float4*)&Bs[bk][bc] = v;
            }
        } else {
            #pragma unroll
            for (int i = 0; i < 2; i++) {
                int li = tid + i * 256;
                int bc = li >> 2;
                int bk = (li & 3) * 4;
                float4 v = *(const float4*)(B + (long long)(colBase + bc) * K + k0 + bk);
                Bs[bk+0][bc] = v.x; Bs[bk+1][bc] = v.y; Bs[bk+2][bc] = v.z; Bs[bk+3][bc] = v.w;
            }
        }
        __syncthreads();
        #pragma unroll
        for (int k = 0; k < BK; k++) {
            float a[8], b[8];
            *(float4*)&a[0] = *(const float4*)&As[k][ty*8];
            *(float4*)&a[4] = *(const float4*)&As[k][ty*8 + 4];
            *(float4*)&b[0] = *(const float4*)&Bs[k][tx*8];
            *(float4*)&b[4] = *(const float4*)&Bs[k][tx*8 + 4];
            #pragma unroll
            for (int i = 0; i < 8; i++)
                #pragma unroll
                for (int j = 0; j < 8; j++) acc[i][j] += a[i] * b[j];
        }
        __syncthreads();
    }

    const int lane = tid & 31;
    float* red = (EPI == 2) ? (z ? red1 : red0) : red0;

    #pragma unroll
    for (int i = 0; i < 8; i++) {
        int r = rowBase + ty * 8 + i;
        int l = r & (LL - 1);
        long long off = (long long)r * N + colBase + tx * 8;

        if (EPI == 0) {
            float4 v0 = { acc[i][0], acc[i][1], acc[i][2], acc[i][3] };
            float4 v1 = { acc[i][4], acc[i][5], acc[i][6], acc[i][7] };
            *(float4*)(C + off)     = v0;
            *(float4*)(C + off + 4) = v1;
        } else if (EPI == 1) {
            float h[8];
            #pragma unroll
            for (int j = 0; j < 8; j++) h[j] = gelu_exact(acc[i][j]);
            float4 v0 = { h[0], h[1], h[2], h[3] };
            float4 v1 = { h[4], h[5], h[6], h[7] };
            *(float4*)(C + off)     = v0;
            *(float4*)(C + off + 4) = v1;
        } else if (EPI == 2) {
            float part = 0.0f;
            #pragma unroll
            for (int j = 0; j < 8; j++)
                part += sigm(aux[off + j] + acc[i][j]);
            #pragma unroll
            for (int o = 8; o > 0; o >>= 1)
                part += __shfl_down_sync(0xffffffffu, part, o, 16);
            if ((lane & 15) == 0) atomicAdd(&red[l], part);
        } else if (EPI == 3) {
            float pl = P[l], sl = S[l], sg = vin[r];
            float h[8]; float part = 0.0f;
            #pragma unroll
            for (int j = 0; j < 8; j++) {
                float u = pl * acc[i][j] + sl * sg;
                h[j] = gelu_exact(u);
                part += h[j];
            }
            float4 v0 = { h[0], h[1], h[2], h[3] };
            float4 v1 = { h[4], h[5], h[6], h[7] };
            *(float4*)(C + off)     = v0;
            *(float4*)(C + off + 4) = v1;
            #pragma unroll
            for (int o = 8; o > 0; o >>= 1)
                part += __shfl_down_sync(0xffffffffu, part, o, 16);
            if ((lane & 15) == 0) atomicAdd(&red[r], part);
        } else if (EPI == 4) {
            float pl = P[l], sl = S[l], hr = vin[r];
            float o0[8];
            #pragma unroll
            for (int j = 0; j < 8; j++)
                o0[j] = aux[off + j] + pl * acc[i][j] + sl * hr;
            float4 v0 = { o0[0], o0[1], o0[2], o0[3] };
            float4 v1 = { o0[4], o0[5], o0[6], o0[7] };
            *(float4*)(C + off)     = v0;
            *(float4*)(C + off + 4) = v1;
        }
    }
}

// ---------------- launcher ----------------
extern "C" void kernel_launch(void* const* d_in, const int* in_sizes, int n_in,
                              void* d_out, int out_size) {
    const float* x       = (const float*)d_in[0];
    const float* conv_w  = (const float*)d_in[1];
    const float* conv_b  = (const float*)d_in[2];
    const float* q_w     = (const float*)d_in[3];
    const float* mem_w1  = (const float*)d_in[4];
    const float* mem_w2  = (const float*)d_in[5];
    const float* eta_w1  = (const float*)d_in[6];
    const float* eta_w2  = (const float*)d_in[7];
    const float* alpha_w1= (const float*)d_in[8];
    const float* alpha_w2= (const float*)d_in[9];
    float* out = (float*)d_out;

    float *xc, *h1, *qb, *hm, *accum, *ps, *qsum;
    cudaGetSymbolAddress((void**)&xc,    g_xc);
    cudaGetSymbolAddress((void**)&h1,    g_h1);
    cudaGetSymbolAddress((void**)&qb,    g_q);
    cudaGetSymbolAddress((void**)&hm,    g_hm);
    cudaGetSymbolAddress((void**)&accum, g_accum);
    cudaGetSymbolAddress((void**)&ps,    g_ps);
    cudaGetSymbolAddress((void**)&qsum,  g_qsum);

    float* hs        = accum;            // [MT]
    float* eta_sum   = accum + MT;       // [LL]
    float* alpha_sum = accum + MT + LL;  // [LL]
    float* Pp = ps;
    float* Ss = ps + LL;

    // 0) zero atomics accumulators
    {
        int n = MT + 2 * LL;
        zero_kernel<<<(n + 255) / 256, 256>>>(accum, n);
    }
    // 1) conv
    conv_kernel<<<(MT * (DD/4) + 255) / 256, 256>>>(x, conv_w, conv_b, xc);

    dim3 grid2(DD / 128, MT / 128, 2);
    dim3 grid1(DD / 128, MT / 128, 1);

    // 2) batched xc @ {eta_w1, alpha_w1} -> gelu -> h1[z]
    gemm_kernel<1, false><<<grid2, 256>>>(xc, 0LL, eta_w1, alpha_w1,
                                          h1, h1 + SZ,
                                          nullptr, nullptr, nullptr, nullptr,
                                          nullptr, nullptr, MT, DD, DD);
    // 3) batched h1[z] @ {eta_w2, alpha_w2} -> sigmoid(xc + .) -> per-l sums
    gemm_kernel<2, false><<<grid2, 256>>>(h1, SZ, eta_w2, alpha_w2,
                                          nullptr, nullptr,
                                          xc, nullptr, nullptr, nullptr,
                                          eta_sum, alpha_sum, MT, DD, DD);
    // 4) xc @ q_w^T -> hm (raw)
    gemm_kernel<0, true><<<grid1, 256>>>(xc, 0LL, q_w, q_w,
                                         hm, hm,
                                         nullptr, nullptr, nullptr, nullptr,
                                         nullptr, nullptr, MT, DD, DD);
    // 5) l2norm -> q, qsum
    l2norm_kernel<<<MT, 128>>>(hm, qb, qsum);
    // 6) scalar scan -> p, s
    scan_kernel<<<1, 32>>>(eta_sum, ps);
    // 7) q @ mem_w1 with affine+gelu epilogue -> hm, hs
    gemm_kernel<3, false><<<grid1, 256>>>(qb, 0LL, mem_w1, mem_w1,
                                          hm, hm,
                                          nullptr, Pp, Ss, qsum,
                                          hs, nullptr, MT, DD, DD);
    // 8) hm @ mem_w2 with final epilogue -> out
    gemm_kernel<4, false><<<grid1, 256>>>(hm, 0LL, mem_w2, mem_w2,
                                          out, out,
                                          qb, Pp, Ss, hs,
                                          nullptr, nullptr, MT, DD, DD);
}

// round 3
// speedup vs baseline: 2.4167x; 2.4167x over previous
#include <cuda_runtime.h>
#include <math.h>
#include <stdint.h>

// Problem sizes (fixed by the reference)
#define BB 8
#define LL 2048
#define DD 512
#define MT (BB*LL)          // 16384 rows
#define SZ ((long long)MT*DD)

// ---------------- scratch (device globals; no allocation allowed) ----------------
__device__ float g_xc[MT*DD];        // conv output
__device__ float g_h1[2*MT*DD];      // gelu(xc@{eta_w1,alpha_w1})
__device__ float g_q[MT*DD];         // normalized q
__device__ float g_hm[MT*DD];        // raw q-gemm out, then gelu(stage1)
__device__ float g_accum[MT + 2*LL]; // [0:MT) hs rowsums, [MT:MT+LL) eta sum, [MT+LL:) alpha sum
__device__ float g_ps[2*LL];         // [0:LL) p,  [LL:2LL) s
__device__ float g_qsum[MT];         // rowsum of q
__device__ float g_wt[7*DD*DD];      // transposed+tf32-rounded weights

__device__ __forceinline__ float gelu_exact(float x) {
    return 0.5f * x * (1.0f + erff(x * 0.70710678118654752f));
}
__device__ __forceinline__ float sigm(float x) {
    return 1.0f / (1.0f + expf(-x));
}
__device__ __forceinline__ uint32_t tf32_bits(float x) {
    uint32_t u; asm("cvt.rna.tf32.f32 %0, %1;" : "=r"(u) : "f"(x)); return u;
}
__device__ __forceinline__ float tf32_round(float x) {
    return __uint_as_float(tf32_bits(x));
}

// ---------------- zero accumulators ----------------
__global__ void zero_kernel(float* a, int n) {
    int i = blockIdx.x * blockDim.x + threadIdx.x;
    if (i < n) a[i] = 0.0f;
}

// ---------------- prep weights: transpose (or copy) + tf32 round ----------------
// slots: 0 eta_w1^T, 1 alpha_w1^T, 2 eta_w2^T, 3 alpha_w2^T, 4 q_w (copy), 5 mem_w1^T, 6 mem_w2^T
__global__ void prep_weights(const float* __restrict__ ew1, const float* __restrict__ aw1,
                             const float* __restrict__ ew2, const float* __restrict__ aw2,
                             const float* __restrict__ qw,  const float* __restrict__ mw1,
                             const float* __restrict__ mw2, float* __restrict__ wt) {
    __shared__ float tile[32][33];
    int zi = blockIdx.z;
    const float* src; bool tr = true;
    switch (zi) {
        case 0: src = ew1; break;
        case 1: src = aw1; break;
        case 2: src = ew2; break;
        case 3: src = aw2; break;
        case 4: src = qw; tr = false; break;
        case 5: src = mw1; break;
        default: src = mw2; break;
    }
    float* dst = wt + (long long)zi * DD * DD;
    int bx = blockIdx.x * 32, by = blockIdx.y * 32;
    int tx = threadIdx.x, ty = threadIdx.y;  // (32, 8)
    if (tr) {
        #pragma unroll
        for (int i = 0; i < 32; i += 8)
            tile[ty + i][tx] = src[(long long)(by + ty + i) * DD + bx + tx];
        __syncthreads();
        #pragma unroll
        for (int i = 0; i < 32; i += 8)
            dst[(long long)(bx + ty + i) * DD + by + tx] = tf32_round(tile[tx][ty + i]);
    } else {
        #pragma unroll
        for (int i = 0; i < 32; i += 8)
            dst[(long long)(by + ty + i) * DD + bx + tx] =
                tf32_round(src[(long long)(by + ty + i) * DD + bx + tx]);
    }
}

// ---------------- causal depthwise conv (k=4, left pad 3) + bias ----------------
__global__ void conv_kernel(const float* __restrict__ x, const float* __restrict__ w,
                            const float* __restrict__ bias, float* __restrict__ xc) {
    int idx = blockIdx.x * blockDim.x + threadIdx.x;
    if (idx >= MT * (DD/4)) return;
    int d4 = idx & 127;
    int r  = idx >> 7;
    int l  = r & (LL-1);
    int d  = d4 * 4;
    float4 out = *(const float4*)(bias + d);
    #pragma unroll
    for (int k = 0; k < 4; k++) {
        int li = l + k - 3;
        if (li >= 0) {
            float4 xv = *(const float4*)(x + (long long)(r + k - 3) * DD + d);
            out.x += xv.x * w[(d+0)*4 + k];
            out.y += xv.y * w[(d+1)*4 + k];
            out.z += xv.z * w[(d+2)*4 + k];
            out.w += xv.w * w[(d+3)*4 + k];
        }
    }
    *(float4*)(xc + (long long)r * DD + d) = out;
}

// ---------------- l2norm rows + rowsum ----------------
__global__ void l2norm_kernel(const float* __restrict__ G, float* __restrict__ q,
                              float* __restrict__ qsum) {
    int r = blockIdx.x;
    int t = threadIdx.x;
    float4 v = ((const float4*)(G + (long long)r * DD))[t];
    float ss = v.x*v.x + v.y*v.y + v.z*v.z + v.w*v.w;
    float sg = v.x + v.y + v.z + v.w;
    #pragma unroll
    for (int o = 16; o > 0; o >>= 1) {
        ss += __shfl_down_sync(0xffffffffu, ss, o);
        sg += __shfl_down_sync(0xffffffffu, sg, o);
    }
    __shared__ float sh_ss[4], sh_sg[4], sh_scale;
    int w = t >> 5;
    if ((t & 31) == 0) { sh_ss[w] = ss; sh_sg[w] = sg; }
    __syncthreads();
    if (t == 0) {
        float S = sh_ss[0] + sh_ss[1] + sh_ss[2] + sh_ss[3];
        float Gs = sh_sg[0] + sh_sg[1] + sh_sg[2] + sh_sg[3];
        float scale = 1.0f / fmaxf(sqrtf(S), 1e-12f);
        sh_scale = scale;
        qsum[r] = Gs * scale;
    }
    __syncthreads();
    float sc = sh_scale;
    float4 o4 = { v.x*sc, v.y*sc, v.z*sc, v.w*sc };
    ((float4*)(q + (long long)r * DD))[t] = o4;
}

// ---------------- parallel affine scan for p_t, s_t ----------------
// s_{t+1} = a_t*s_t + b_t (b_t = -0.01*e_t), p_{t+1} = a_t*p_t.
// Inclusive Hillis-Steele over (A,b) affine composition; PS[t] = prefix over first t.
__global__ void scan_kernel(const float* __restrict__ red, float* __restrict__ PS) {
    __shared__ float Aa[2][LL];
    __shared__ float Bb[2][LL];
    const float inv = 1.0f / (float)(BB * DD);
    int t = threadIdx.x;  // 1024
    #pragma unroll
    for (int h = 0; h < 2; h++) {
        int e = t + h * 1024;
        Aa[0][e] = red[LL + e] * inv;        // alpha mean
        Bb[0][e] = -0.01f * red[e] * inv;    // -0.01 * eta mean
    }
    int cur = 0;
    for (int d = 1; d < LL; d <<= 1) {
        __syncthreads();
        #pragma unroll
        for (int h = 0; h < 2; h++) {
            int e = t + h * 1024;
            float A2 = Aa[cur][e], B2 = Bb[cur][e];
            if (e >= d) {
                float A1 = Aa[cur][e - d], B1 = Bb[cur][e - d];
                // left prefix then right segment: s' = A2*(A1*s + B1) + B2
                B2 = A2 * B1 + B2;
                A2 = A1 * A2;
            }
            Aa[cur ^ 1][e] = A2;
            Bb[cur ^ 1][e] = B2;
        }
        cur ^= 1;
    }
    __syncthreads();
    #pragma unroll
    for (int h = 0; h < 2; h++) {
        int e = t + h * 1024;
        PS[e]      = (e == 0) ? 1.0f : Aa[cur][e - 1];
        PS[LL + e] = (e == 0) ? 0.0f : Bb[cur][e - 1];
    }
}

// ---------------- tf32 mma.sync GEMM, fused epilogues ----------------
// C[128x128 tile] = A(rows, K=512) @ Bt(cols, K=512)^T  (both row-major, K contiguous)
// EPI 0: C = acc
// EPI 1: C = gelu(acc)
// EPI 2: no store; atomicAdd red[(r&2047)] += sum_cols sigmoid(aux[r,c]+acc)
// EPI 3: h = gelu(P[l]*acc + S[l]*vin[r]); C = h; atomicAdd red0[r] += sum_cols h
// EPI 4: C = aux[r,c] + P[l]*acc + S[l]*vin[r]
#define SW 36   // smem row stride (words): bank = (row*4 + col) % 32 -> conflict-free frags

template<int EPI>
__global__ __launch_bounds__(256)
void gemm_mma(const float* __restrict__ A, long long Astride,
              const float* __restrict__ Bt0, const float* __restrict__ Bt1,
              float* C0, float* C1,
              const float* __restrict__ aux,
              const float* __restrict__ P, const float* __restrict__ S,
              const float* __restrict__ vin,
              float* red0, float* red1) {
    __shared__ uint32_t As[128 * SW];
    __shared__ uint32_t Bs[128 * SW];

    const int tid  = threadIdx.x;
    const int lane = tid & 31, warp = tid >> 5;
    const int wm = warp >> 2, wn = warp & 3;       // 2 x 4 warp grid
    const int qr = lane >> 2, qk = lane & 3;
    const int rowBase = blockIdx.y * 128;
    const int colBase = blockIdx.x * 128;
    const int z = blockIdx.z;
    const float* Ab = A + (long long)z * Astride;
    const float* Bt = z ? Bt1 : Bt0;
    float* C        = z ? C1 : C0;

    float acc[4][4][4];
    #pragma unroll
    for (int mf = 0; mf < 4; mf++)
        #pragma unroll
        for (int nf = 0; nf < 4; nf++)
            #pragma unroll
            for (int i = 0; i < 4; i++) acc[mf][nf][i] = 0.0f;

    // per-thread load coords (4 float4 each for A and B per BK=32 chunk)
    int lrow[4], lcol[4];
    #pragma unroll
    for (int i = 0; i < 4; i++) {
        int li = i * 256 + tid;
        lrow[i] = li >> 3;
        lcol[i] = (li & 7) * 4;
    }

    float4 pa[4], pb[4];
    #pragma unroll
    for (int i = 0; i < 4; i++) {
        pa[i] = *(const float4*)(Ab + (long long)(rowBase + lrow[i]) * DD + lcol[i]);
        pb[i] = *(const float4*)(Bt + (long long)(colBase + lrow[i]) * DD + lcol[i]);
    }

    for (int kc = 0; kc < 16; kc++) {
        // store current chunk to smem (A: cvt to tf32 rna; B pre-rounded)
        #pragma unroll
        for (int i = 0; i < 4; i++) {
            uint32_t* ad = &As[lrow[i] * SW + lcol[i]];
            ad[0] = tf32_bits(pa[i].x); ad[1] = tf32_bits(pa[i].y);
            ad[2] = tf32_bits(pa[i].z); ad[3] = tf32_bits(pa[i].w);
            uint32_t* bd = &Bs[lrow[i] * SW + lcol[i]];
            bd[0] = __float_as_uint(pb[i].x); bd[1] = __float_as_uint(pb[i].y);
            bd[2] = __float_as_uint(pb[i].z); bd[3] = __float_as_uint(pb[i].w);
        }
        __syncthreads();
        if (kc < 15) {
            int k0 = (kc + 1) * 32;
            #pragma unroll
            for (int i = 0; i < 4; i++) {
                pa[i] = *(const float4*)(Ab + (long long)(rowBase + lrow[i]) * DD + k0 + lcol[i]);
                pb[i] = *(const float4*)(Bt + (long long)(colBase + lrow[i]) * DD + k0 + lcol[i]);
            }
        }
        #pragma unroll
        for (int ks = 0; ks < 4; ks++) {
            uint32_t a[4][4], b[4][2];
            const uint32_t* ap = &As[(wm * 64 + qr) * SW + ks * 8 + qk];
            #pragma unroll
            for (int mf = 0; mf < 4; mf++) {
                a[mf][0] = ap[(mf * 16    ) * SW];
                a[mf][1] = ap[(mf * 16 + 8) * SW];
                a[mf][2] = ap[(mf * 16    ) * SW + 4];
                a[mf][3] = ap[(mf * 16 + 8) * SW + 4];
            }
            const uint32_t* bp = &Bs[(wn * 32 + qr) * SW + ks * 8 + qk];
            #pragma unroll
            for (int nf = 0; nf < 4; nf++) {
                b[nf][0] = bp[nf * 8 * SW];
                b[nf][1] = bp[nf * 8 * SW + 4];
            }
            #pragma unroll
            for (int mf = 0; mf < 4; mf++)
                #pragma unroll
                for (int nf = 0; nf < 4; nf++)
                    asm volatile(
                        "mma.sync.aligned.m16n8k8.row.col.f32.tf32.tf32.f32 "
                        "{%0,%1,%2,%3}, {%4,%5,%6,%7}, {%8,%9}, {%0,%1,%2,%3};"
                        : "+f"(acc[mf][nf][0]), "+f"(acc[mf][nf][1]),
                          "+f"(acc[mf][nf][2]), "+f"(acc[mf][nf][3])
                        : "r"(a[mf][0]), "r"(a[mf][1]), "r"(a[mf][2]), "r"(a[mf][3]),
                          "r"(b[nf][0]), "r"(b[nf][1]));
        }
        __syncthreads();
    }

    // ---- epilogue ----
    float* red = (EPI == 2) ? (z ? red1 : red0) : red0;
    const int cBase = colBase + wn * 32 + 2 * qk;

    #pragma unroll
    for (int mf = 0; mf < 4; mf++) {
        #pragma unroll
        for (int half = 0; half < 2; half++) {
            int r = rowBase + wm * 64 + mf * 16 + qr + half * 8;
            int l = r & (LL - 1);
            int ci = half * 2;   // acc index offset: c0,c1 (row) / c2,c3 (row+8)
            float part = 0.0f;
            float pl = 0.f, sl = 0.f, vv = 0.f;
            if (EPI == 3 || EPI == 4) { pl = P[l]; sl = S[l]; vv = vin[r]; }

            #pragma unroll
            for (int nf = 0; nf < 4; nf++) {
                float v0 = acc[mf][nf][ci], v1 = acc[mf][nf][ci + 1];
                long long off = (long long)r * DD + cBase + nf * 8;
                if (EPI == 0) {
                    float2 o = { v0, v1 };
                    *(float2*)(C + off) = o;
                } else if (EPI == 1) {
                    float2 o = { gelu_exact(v0), gelu_exact(v1) };
                    *(float2*)(C + off) = o;
                } else if (EPI == 2) {
                    float2 a2 = *(const float2*)(aux + off);
                    part += sigm(a2.x + v0) + sigm(a2.y + v1);
                } else if (EPI == 3) {
                    float h0 = gelu_exact(pl * v0 + sl * vv);
                    float h1 = gelu_exact(pl * v1 + sl * vv);
                    part += h0 + h1;
                    float2 o = { h0, h1 };
                    *(float2*)(C + off) = o;
                } else if (EPI == 4) {
                    float2 a2 = *(const float2*)(aux + off);
                    float2 o = { a2.x + pl * v0 + sl * vv,
                                 a2.y + pl * v1 + sl * vv };
                    *(float2*)(C + off) = o;
                }
            }
            if (EPI == 2 || EPI == 3) {
                part += __shfl_xor_sync(0xffffffffu, part, 1);
                part += __shfl_xor_sync(0xffffffffu, part, 2);
                if (qk == 0) {
                    if (EPI == 2) atomicAdd(&red[l], part);
                    else          atomicAdd(&red[r], part);
                }
            }
        }
    }
}

// ---------------- launcher ----------------
extern "C" void kernel_launch(void* const* d_in, const int* in_sizes, int n_in,
                              void* d_out, int out_size) {
    const float* x        = (const float*)d_in[0];
    const float* conv_w   = (const float*)d_in[1];
    const float* conv_b   = (const float*)d_in[2];
    const float* q_w      = (const float*)d_in[3];
    const float* mem_w1   = (const float*)d_in[4];
    const float* mem_w2   = (const float*)d_in[5];
    const float* eta_w1   = (const float*)d_in[6];
    const float* eta_w2   = (const float*)d_in[7];
    const float* alpha_w1 = (const float*)d_in[8];
    const float* alpha_w2 = (const float*)d_in[9];
    float* out = (float*)d_out;

    float *xc, *h1, *qb, *hm, *accum, *ps, *qsum, *wt;
    cudaGetSymbolAddress((void**)&xc,    g_xc);
    cudaGetSymbolAddress((void**)&h1,    g_h1);
    cudaGetSymbolAddress((void**)&qb,    g_q);
    cudaGetSymbolAddress((void**)&hm,    g_hm);
    cudaGetSymbolAddress((void**)&accum, g_accum);
    cudaGetSymbolAddress((void**)&ps,    g_ps);
    cudaGetSymbolAddress((void**)&qsum,  g_qsum);
    cudaGetSymbolAddress((void**)&wt,    g_wt);

    float* hs        = accum;
    float* eta_sum   = accum + MT;
    float* alpha_sum = accum + MT + LL;
    float* Pp = ps;
    float* Ss = ps + LL;

    // 0) zero atomic accumulators
    {
        int n = MT + 2 * LL;
        zero_kernel<<<(n + 255) / 256, 256>>>(accum, n);
    }
    // 0b) transpose + tf32-round weights
    prep_weights<<<dim3(16, 16, 7), dim3(32, 8)>>>(eta_w1, alpha_w1, eta_w2, alpha_w2,
                                                   q_w, mem_w1, mem_w2, wt);
    // 1) conv
    conv_kernel<<<(MT * (DD/4) + 255) / 256, 256>>>(x, conv_w, conv_b, xc);

    dim3 grid2(DD / 128, MT / 128, 2);
    dim3 grid1(DD / 128, MT / 128, 1);
    float* wt0 = wt + 0LL * DD * DD;  // eta_w1^T
    float* wt1 = wt + 1LL * DD * DD;  // alpha_w1^T
    float* wt2 = wt + 2LL * DD * DD;  // eta_w2^T
    float* wt3 = wt + 3LL * DD * DD;  // alpha_w2^T
    float* wt4 = wt + 4LL * DD * DD;  // q_w (rounded)
    float* wt5 = wt + 5LL * DD * DD;  // mem_w1^T
    float* wt6 = wt + 6LL * DD * DD;  // mem_w2^T

    // 2) batched xc @ {eta_w1, alpha_w1} -> gelu -> h1[z]
    gemm_mma<1><<<grid2, 256>>>(xc, 0LL, wt0, wt1, h1, h1 + SZ,
                                nullptr, nullptr, nullptr, nullptr,
                                nullptr, nullptr);
    // 3) batched h1[z] @ {eta_w2, alpha_w2} -> sigmoid(xc + .) -> per-l sums
    gemm_mma<2><<<grid2, 256>>>(h1, SZ, wt2, wt3, nullptr, nullptr,
                                xc, nullptr, nullptr, nullptr,
                                eta_sum, alpha_sum);
    // 4) xc @ q_w^T -> hm (raw)
    gemm_mma<0><<<grid1, 256>>>(xc, 0LL, wt4, wt4, hm, hm,
                                nullptr, nullptr, nullptr, nullptr,
                                nullptr, nullptr);
    // 5) l2norm -> q, qsum
    l2norm_kernel<<<MT, 128>>>(hm, qb, qsum);
    // 6) parallel affine scan -> p, s
    scan_kernel<<<1, 1024>>>(eta_sum, ps);
    // 7) q @ mem_w1 with affine+gelu epilogue -> hm, hs
    gemm_mma<3><<<grid1, 256>>>(qb, 0LL, wt5, wt5, hm, hm,
                                nullptr, Pp, Ss, qsum,
                                hs, nullptr);
    // 8) hm @ mem_w2 with final epilogue -> out
    gemm_mma<4><<<grid1, 256>>>(hm, 0LL, wt6, wt6, out, out,
                                qb, Pp, Ss, hs,
                                nullptr, nullptr);
}

// round 4
// speedup vs baseline: 3.1144x; 1.2887x over previous
#include <cuda_runtime.h>
#include <math.h>
#include <stdint.h>

// Problem sizes (fixed by the reference)
#define BB 8
#define LL 2048
#define DD 512
#define MT (BB*LL)          // 16384 rows
#define SZ ((long long)MT*DD)

// ---------------- scratch (device globals; no allocation allowed) ----------------
__device__ float g_xc[MT*DD];        // conv output (full fp32, aux for EPI2)
__device__ float g_xct[MT*DD];       // conv output, tf32-rounded (GEMM A)
__device__ float g_h1[2*MT*DD];      // tf32(gelu(xc@{eta_w1,alpha_w1}))
__device__ float g_q[MT*DD];         // normalized q (full fp32, aux for EPI4)
__device__ float g_qt[MT*DD];        // normalized q, tf32-rounded (GEMM A)
__device__ float g_hm[MT*DD];        // raw q-gemm out, then tf32(gelu(stage1))
__device__ float g_accum[MT + 2*LL]; // [0:MT) hs rowsums, [MT:MT+LL) eta sum, [MT+LL:) alpha sum
__device__ float g_ps[2*LL];         // [0:LL) p,  [LL:2LL) s
__device__ float g_qsum[MT];         // rowsum of q
__device__ float g_wt[7*DD*DD];      // transposed+tf32-rounded weights

__device__ __forceinline__ float gelu_exact(float x) {
    return 0.5f * x * (1.0f + erff(x * 0.70710678118654752f));
}
__device__ __forceinline__ float sigm(float x) {
    return 1.0f / (1.0f + expf(-x));
}
__device__ __forceinline__ uint32_t tf32_bits(float x) {
    uint32_t u; asm("cvt.rna.tf32.f32 %0, %1;" : "=r"(u) : "f"(x)); return u;
}
__device__ __forceinline__ float tf32_round(float x) {
    return __uint_as_float(tf32_bits(x));
}
__device__ __forceinline__ uint32_t smem_u32(const void* p) {
    uint32_t a;
    asm("{ .reg .u64 t; cvta.to.shared.u64 t, %1; cvt.u32.u64 %0, t; }" : "=r"(a) : "l"(p));
    return a;
}

// ---------------- zero accumulators ----------------
__global__ void zero_kernel(float* a, int n) {
    int i = blockIdx.x * blockDim.x + threadIdx.x;
    if (i < n) a[i] = 0.0f;
}

// ---------------- prep weights: transpose (or copy) + tf32 round ----------------
// slots: 0 eta_w1^T, 1 alpha_w1^T, 2 eta_w2^T, 3 alpha_w2^T, 4 q_w (copy), 5 mem_w1^T, 6 mem_w2^T
__global__ void prep_weights(const float* __restrict__ ew1, const float* __restrict__ aw1,
                             const float* __restrict__ ew2, const float* __restrict__ aw2,
                             const float* __restrict__ qw,  const float* __restrict__ mw1,
                             const float* __restrict__ mw2, float* __restrict__ wt) {
    __shared__ float tile[32][33];
    int zi = blockIdx.z;
    const float* src; bool tr = true;
    switch (zi) {
        case 0: src = ew1; break;
        case 1: src = aw1; break;
        case 2: src = ew2; break;
        case 3: src = aw2; break;
        case 4: src = qw; tr = false; break;
        case 5: src = mw1; break;
        default: src = mw2; break;
    }
    float* dst = wt + (long long)zi * DD * DD;
    int bx = blockIdx.x * 32, by = blockIdx.y * 32;
    int tx = threadIdx.x, ty = threadIdx.y;  // (32, 8)
    if (tr) {
        #pragma unroll
        for (int i = 0; i < 32; i += 8)
            tile[ty + i][tx] = src[(long long)(by + ty + i) * DD + bx + tx];
        __syncthreads();
        #pragma unroll
        for (int i = 0; i < 32; i += 8)
            dst[(long long)(bx + ty + i) * DD + by + tx] = tf32_round(tile[tx][ty + i]);
    } else {
        #pragma unroll
        for (int i = 0; i < 32; i += 8)
            dst[(long long)(by + ty + i) * DD + bx + tx] =
                tf32_round(src[(long long)(by + ty + i) * DD + bx + tx]);
    }
}

// ---------------- causal depthwise conv (k=4, left pad 3) + bias ----------------
__global__ void conv_kernel(const float* __restrict__ x, const float* __restrict__ w,
                            const float* __restrict__ bias, float* __restrict__ xc,
                            float* __restrict__ xct) {
    int idx = blockIdx.x * blockDim.x + threadIdx.x;
    if (idx >= MT * (DD/4)) return;
    int d4 = idx & 127;
    int r  = idx >> 7;
    int l  = r & (LL-1);
    int d  = d4 * 4;
    float4 out = *(const float4*)(bias + d);
    #pragma unroll
    for (int k = 0; k < 4; k++) {
        int li = l + k - 3;
        if (li >= 0) {
            float4 xv = *(const float4*)(x + (long long)(r + k - 3) * DD + d);
            out.x += xv.x * w[(d+0)*4 + k];
            out.y += xv.y * w[(d+1)*4 + k];
            out.z += xv.z * w[(d+2)*4 + k];
            out.w += xv.w * w[(d+3)*4 + k];
        }
    }
    long long off = (long long)r * DD + d;
    *(float4*)(xc + off) = out;
    float4 rt = { tf32_round(out.x), tf32_round(out.y), tf32_round(out.z), tf32_round(out.w) };
    *(float4*)(xct + off) = rt;
}

// ---------------- l2norm rows + rowsum (writes full q and tf32 copy) ----------------
__global__ void l2norm_kernel(const float* __restrict__ G, float* __restrict__ q,
                              float* __restrict__ qt, float* __restrict__ qsum) {
    int r = blockIdx.x;
    int t = threadIdx.x;
    float4 v = ((const float4*)(G + (long long)r * DD))[t];
    float ss = v.x*v.x + v.y*v.y + v.z*v.z + v.w*v.w;
    float sg = v.x + v.y + v.z + v.w;
    #pragma unroll
    for (int o = 16; o > 0; o >>= 1) {
        ss += __shfl_down_sync(0xffffffffu, ss, o);
        sg += __shfl_down_sync(0xffffffffu, sg, o);
    }
    __shared__ float sh_ss[4], sh_sg[4], sh_scale;
    int w = t >> 5;
    if ((t & 31) == 0) { sh_ss[w] = ss; sh_sg[w] = sg; }
    __syncthreads();
    if (t == 0) {
        float S = sh_ss[0] + sh_ss[1] + sh_ss[2] + sh_ss[3];
        float Gs = sh_sg[0] + sh_sg[1] + sh_sg[2] + sh_sg[3];
        float scale = 1.0f / fmaxf(sqrtf(S), 1e-12f);
        sh_scale = scale;
        qsum[r] = Gs * scale;
    }
    __syncthreads();
    float sc = sh_scale;
    float4 o4 = { v.x*sc, v.y*sc, v.z*sc, v.w*sc };
    ((float4*)(q + (long long)r * DD))[t] = o4;
    float4 r4 = { tf32_round(o4.x), tf32_round(o4.y), tf32_round(o4.z), tf32_round(o4.w) };
    ((float4*)(qt + (long long)r * DD))[t] = r4;
}

// ---------------- parallel affine scan for p_t, s_t ----------------
__global__ void scan_kernel(const float* __restrict__ red, float* __restrict__ PS) {
    __shared__ float Aa[2][LL];
    __shared__ float Bb[2][LL];
    const float inv = 1.0f / (float)(BB * DD);
    int t = threadIdx.x;  // 1024
    #pragma unroll
    for (int h = 0; h < 2; h++) {
        int e = t + h * 1024;
        Aa[0][e] = red[LL + e] * inv;        // alpha mean
        Bb[0][e] = -0.01f * red[e] * inv;    // -0.01 * eta mean
    }
    int cur = 0;
    for (int d = 1; d < LL; d <<= 1) {
        __syncthreads();
        #pragma unroll
        for (int h = 0; h < 2; h++) {
            int e = t + h * 1024;
            float A2 = Aa[cur][e], B2 = Bb[cur][e];
            if (e >= d) {
                float A1 = Aa[cur][e - d], B1 = Bb[cur][e - d];
                B2 = A2 * B1 + B2;
                A2 = A1 * A2;
            }
            Aa[cur ^ 1][e] = A2;
            Bb[cur ^ 1][e] = B2;
        }
        cur ^= 1;
    }
    __syncthreads();
    #pragma unroll
    for (int h = 0; h < 2; h++) {
        int e = t + h * 1024;
        PS[e]      = (e == 0) ? 1.0f : Aa[cur][e - 1];
        PS[LL + e] = (e == 0) ? 0.0f : Bb[cur][e - 1];
    }
}

// ---------------- tf32 mma.sync GEMM, cp.async 3-stage pipeline ----------------
// All operands pre-rounded to tf32 in gmem. C tile 128x128, BK=32, 8 warps 64x32.
// EPI 0: C = acc
// EPI 1: C = tf32(gelu(acc))
// EPI 2: no store; atomicAdd red[(r&2047)] += sum_cols sigmoid(aux[r,c]+acc)
// EPI 3: h = gelu(P[l]*acc + S[l]*vin[r]); C = tf32(h); atomicAdd red0[r] += sum h
// EPI 4: C = aux[r,c] + P[l]*acc + S[l]*vin[r]
#define SW 36           // smem row stride (words): conflict-free frag gathers
#define STG_WORDS (128*SW)          // 4608 words = 18432 B per matrix-stage
#define SMEM_GB (6*STG_WORDS*4)     // 3 stages x (A+B) = 110592 B

template<int EPI>
__global__ __launch_bounds__(256, 2)
void gemm_mma(const float* __restrict__ A, long long Astride,
              const float* __restrict__ Bt0, const float* __restrict__ Bt1,
              float* C0, float* C1,
              const float* __restrict__ aux,
              const float* __restrict__ P, const float* __restrict__ S,
              const float* __restrict__ vin,
              float* red0, float* red1) {
    extern __shared__ uint32_t smemBuf[];
    const uint32_t sbase = smem_u32(smemBuf);

    const int tid  = threadIdx.x;
    const int lane = tid & 31, warp = tid >> 5;
    const int wm = warp >> 2, wn = warp & 3;       // 2 x 4 warp grid
    const int qr = lane >> 2, qk = lane & 3;
    const int rowBase = blockIdx.y * 128;
    const int colBase = blockIdx.x * 128;
    const int z = blockIdx.z;
    const float* Ab = A + (long long)z * Astride;
    const float* Bt = z ? Bt1 : Bt0;
    float* C        = z ? C1 : C0;

    float acc[4][4][4];
    #pragma unroll
    for (int mf = 0; mf < 4; mf++)
        #pragma unroll
        for (int nf = 0; nf < 4; nf++)
            #pragma unroll
            for (int i = 0; i < 4; i++) acc[mf][nf][i] = 0.0f;

    // per-thread load coords (4 x 16B each for A and B per BK=32 chunk)
    const int lr = tid >> 3;              // base row (same for all 4, +32*i)
    const int lc = (tid & 7) * 4;

    auto issue = [&](int kc, int s) {
        const int k0 = kc * 32;
        const uint32_t abase = sbase + s * (STG_WORDS * 4);
        const uint32_t bbase = sbase + (3 + s) * (STG_WORDS * 4);
        #pragma unroll
        for (int i = 0; i < 4; i++) {
            int row = lr + i * 32;
            const float* ga = Ab + (long long)(rowBase + row) * DD + k0 + lc;
            const float* gb = Bt + (long long)(colBase + row) * DD + k0 + lc;
            uint32_t da = abase + (row * SW + lc) * 4;
            uint32_t db = bbase + (row * SW + lc) * 4;
            asm volatile("cp.async.cg.shared.global [%0], [%1], 16;"
                :: "r"(da), "l"(__cvta_generic_to_global(ga)));
            asm volatile("cp.async.cg.shared.global [%0], [%1], 16;"
                :: "r"(db), "l"(__cvta_generic_to_global(gb)));
        }
        asm volatile("cp.async.commit_group;" ::: "memory");
    };

    issue(0, 0);
    issue(1, 1);

    int s = 0;
    for (int kc = 0; kc < 16; kc++) {
        asm volatile("cp.async.wait_group 1;" ::: "memory");
        __syncthreads();
        const uint32_t* As = smemBuf + s * STG_WORDS;
        const uint32_t* Bs = smemBuf + (3 + s) * STG_WORDS;

        #pragma unroll
        for (int ks = 0; ks < 4; ks++) {
            uint32_t a[4][4], b[4][2];
            const uint32_t* ap = &As[(wm * 64 + qr) * SW + ks * 8 + qk];
            #pragma unroll
            for (int mf = 0; mf < 4; mf++) {
                a[mf][0] = ap[(mf * 16    ) * SW];
                a[mf][1] = ap[(mf * 16 + 8) * SW];
                a[mf][2] = ap[(mf * 16    ) * SW + 4];
                a[mf][3] = ap[(mf * 16 + 8) * SW + 4];
            }
            const uint32_t* bp = &Bs[(wn * 32 + qr) * SW + ks * 8 + qk];
            #pragma unroll
            for (int nf = 0; nf < 4; nf++) {
                b[nf][0] = bp[nf * 8 * SW];
                b[nf][1] = bp[nf * 8 * SW + 4];
            }
            #pragma unroll
            for (int mf = 0; mf < 4; mf++)
                #pragma unroll
                for (int nf = 0; nf < 4; nf++)
                    asm volatile(
                        "mma.sync.aligned.m16n8k8.row.col.f32.tf32.tf32.f32 "
                        "{%0,%1,%2,%3}, {%4,%5,%6,%7}, {%8,%9}, {%0,%1,%2,%3};"
                        : "+f"(acc[mf][nf][0]), "+f"(acc[mf][nf][1]),
                          "+f"(acc[mf][nf][2]), "+f"(acc[mf][nf][3])
                        : "r"(a[mf][0]), "r"(a[mf][1]), "r"(a[mf][2]), "r"(a[mf][3]),
                          "r"(b[nf][0]), "r"(b[nf][1]));
        }
        if (kc < 14) issue(kc + 2, (s + 2) % 3);
        s = (s + 1) % 3;
    }

    // ---- epilogue ----
    float* red = (EPI == 2) ? (z ? red1 : red0) : red0;
    const int cBase = colBase + wn * 32 + 2 * qk;

    #pragma unroll
    for (int mf = 0; mf < 4; mf++) {
        #pragma unroll
        for (int half = 0; half < 2; half++) {
            int r = rowBase + wm * 64 + mf * 16 + qr + half * 8;
            int l = r & (LL - 1);
            int ci = half * 2;
            float part = 0.0f;
            float pl = 0.f, sl = 0.f, vv = 0.f;
            if (EPI == 3 || EPI == 4) { pl = P[l]; sl = S[l]; vv = vin[r]; }

            #pragma unroll
            for (int nf = 0; nf < 4; nf++) {
                float v0 = acc[mf][nf][ci], v1 = acc[mf][nf][ci + 1];
                long long off = (long long)r * DD + cBase + nf * 8;
                if (EPI == 0) {
                    float2 o = { v0, v1 };
                    *(float2*)(C + off) = o;
                } else if (EPI == 1) {
                    float2 o = { tf32_round(gelu_exact(v0)), tf32_round(gelu_exact(v1)) };
                    *(float2*)(C + off) = o;
                } else if (EPI == 2) {
                    float2 a2 = *(const float2*)(aux + off);
                    part += sigm(a2.x + v0) + sigm(a2.y + v1);
                } else if (EPI == 3) {
                    float h0 = gelu_exact(pl * v0 + sl * vv);
                    float h1 = gelu_exact(pl * v1 + sl * vv);
                    part += h0 + h1;
                    float2 o = { tf32_round(h0), tf32_round(h1) };
                    *(float2*)(C + off) = o;
                } else if (EPI == 4) {
                    float2 a2 = *(const float2*)(aux + off);
                    float2 o = { a2.x + pl * v0 + sl * vv,
                                 a2.y + pl * v1 + sl * vv };
                    *(float2*)(C + off) = o;
                }
            }
            if (EPI == 2 || EPI == 3) {
                part += __shfl_xor_sync(0xffffffffu, part, 1);
                part += __shfl_xor_sync(0xffffffffu, part, 2);
                if (qk == 0) {
                    if (EPI == 2) atomicAdd(&red[l], part);
                    else          atomicAdd(&red[r], part);
                }
            }
        }
    }
}

// ---------------- launcher ----------------
extern "C" void kernel_launch(void* const* d_in, const int* in_sizes, int n_in,
                              void* d_out, int out_size) {
    const float* x        = (const float*)d_in[0];
    const float* conv_w   = (const float*)d_in[1];
    const float* conv_b   = (const float*)d_in[2];
    const float* q_w      = (const float*)d_in[3];
    const float* mem_w1   = (const float*)d_in[4];
    const float* mem_w2   = (const float*)d_in[5];
    const float* eta_w1   = (const float*)d_in[6];
    const float* eta_w2   = (const float*)d_in[7];
    const float* alpha_w1 = (const float*)d_in[8];
    const float* alpha_w2 = (const float*)d_in[9];
    float* out = (float*)d_out;

    float *xc, *xct, *h1, *qb, *qt, *hm, *accum, *ps, *qsum, *wt;
    cudaGetSymbolAddress((void**)&xc,    g_xc);
    cudaGetSymbolAddress((void**)&xct,   g_xct);
    cudaGetSymbolAddress((void**)&h1,    g_h1);
    cudaGetSymbolAddress((void**)&qb,    g_q);
    cudaGetSymbolAddress((void**)&qt,    g_qt);
    cudaGetSymbolAddress((void**)&hm,    g_hm);
    cudaGetSymbolAddress((void**)&accum, g_accum);
    cudaGetSymbolAddress((void**)&ps,    g_ps);
    cudaGetSymbolAddress((void**)&qsum,  g_qsum);
    cudaGetSymbolAddress((void**)&wt,    g_wt);

    float* hs        = accum;
    float* eta_sum   = accum + MT;
    float* alpha_sum = accum + MT + LL;
    float* Pp = ps;
    float* Ss = ps + LL;

    static bool attr_done = false;
    if (!attr_done) {
        cudaFuncSetAttribute(gemm_mma<0>, cudaFuncAttributeMaxDynamicSharedMemorySize, SMEM_GB);
        cudaFuncSetAttribute(gemm_mma<1>, cudaFuncAttributeMaxDynamicSharedMemorySize, SMEM_GB);
        cudaFuncSetAttribute(gemm_mma<2>, cudaFuncAttributeMaxDynamicSharedMemorySize, SMEM_GB);
        cudaFuncSetAttribute(gemm_mma<3>, cudaFuncAttributeMaxDynamicSharedMemorySize, SMEM_GB);
        cudaFuncSetAttribute(gemm_mma<4>, cudaFuncAttributeMaxDynamicSharedMemorySize, SMEM_GB);
        attr_done = true;
    }

    // 0) zero atomic accumulators
    {
        int n = MT + 2 * LL;
        zero_kernel<<<(n + 255) / 256, 256>>>(accum, n);
    }
    // 0b) transpose + tf32-round weights
    prep_weights<<<dim3(16, 16, 7), dim3(32, 8)>>>(eta_w1, alpha_w1, eta_w2, alpha_w2,
                                                   q_w, mem_w1, mem_w2, wt);
    // 1) conv (writes full xc + rounded xct)
    conv_kernel<<<(MT * (DD/4) + 255) / 256, 256>>>(x, conv_w, conv_b, xc, xct);

    dim3 grid2(DD / 128, MT / 128, 2);
    dim3 grid1(DD / 128, MT / 128, 1);
    float* wt0 = wt + 0LL * DD * DD;  // eta_w1^T
    float* wt1 = wt + 1LL * DD * DD;  // alpha_w1^T
    float* wt2 = wt + 2LL * DD * DD;  // eta_w2^T
    float* wt3 = wt + 3LL * DD * DD;  // alpha_w2^T
    float* wt4 = wt + 4LL * DD * DD;  // q_w (rounded)
    float* wt5 = wt + 5LL * DD * DD;  // mem_w1^T
    float* wt6 = wt + 6LL * DD * DD;  // mem_w2^T

    // 2) batched xct @ {eta_w1, alpha_w1} -> tf32(gelu) -> h1[z]
    gemm_mma<1><<<grid2, 256, SMEM_GB>>>(xct, 0LL, wt0, wt1, h1, h1 + SZ,
                                         nullptr, nullptr, nullptr, nullptr,
                                         nullptr, nullptr);
    // 3) batched h1[z] @ {eta_w2, alpha_w2} -> sigmoid(xc + .) -> per-l sums
    gemm_mma<2><<<grid2, 256, SMEM_GB>>>(h1, SZ, wt2, wt3, nullptr, nullptr,
                                         xc, nullptr, nullptr, nullptr,
                                         eta_sum, alpha_sum);
    // 4) xct @ q_w^T -> hm (raw)
    gemm_mma<0><<<grid1, 256, SMEM_GB>>>(xct, 0LL, wt4, wt4, hm, hm,
                                         nullptr, nullptr, nullptr, nullptr,
                                         nullptr, nullptr);
    // 5) l2norm -> q (full), qt (tf32), qsum
    l2norm_kernel<<<MT, 128>>>(hm, qb, qt, qsum);
    // 6) parallel affine scan -> p, s
    scan_kernel<<<1, 1024>>>(eta_sum, ps);
    // 7) qt @ mem_w1 with affine+gelu epilogue -> hm (tf32), hs
    gemm_mma<3><<<grid1, 256, SMEM_GB>>>(qt, 0LL, wt5, wt5, hm, hm,
                                         nullptr, Pp, Ss, qsum,
                                         hs, nullptr);
    // 8) hm @ mem_w2 with final epilogue -> out
    gemm_mma<4><<<grid1, 256, SMEM_GB>>>(hm, 0LL, wt6, wt6, out, out,
                                         qb, Pp, Ss, hs,
                                         nullptr, nullptr);
}